// round 1
// baseline (speedup 1.0000x reference)
#include <cuda_runtime.h>
#include <cuda_bf16.h>

#define BATCH 1024
#define NNODE 360
#define NHEAD 8
#define DFEAT 256

// softmax weights, duplicated as (a,a) pairs for packed f32x2 FMA
__device__ float2 g_attn2[NNODE * NHEAD];

// ---------------------------------------------------------------------------
// Kernel 1: attn = softmax(w, axis=0), stored duplicated.  1 block, 256 thr.
// Deterministic reduction: warp h sums head h in fixed order + shfl tree.
// ---------------------------------------------------------------------------
__global__ void softmax_k(const float* __restrict__ w) {
    __shared__ float s_e[NNODE * NHEAD];
    __shared__ float s_sum[NHEAD];
    const int t = threadIdx.x;

    for (int i = t; i < NNODE * NHEAD; i += 256)
        s_e[i] = expf(w[i]);
    __syncthreads();

    const int wid = t >> 5;      // warp id == head id (8 warps)
    const int lane = t & 31;
    float partial = 0.f;
    for (int n = lane; n < NNODE; n += 32)
        partial += s_e[n * NHEAD + wid];
    #pragma unroll
    for (int off = 16; off > 0; off >>= 1)
        partial += __shfl_down_sync(0xFFFFFFFFu, partial, off);
    if (lane == 0) s_sum[wid] = partial;
    __syncthreads();

    for (int i = t; i < NNODE * NHEAD; i += 256) {
        float a = s_e[i] / s_sum[i & 7];
        g_attn2[i] = make_float2(a, a);
    }
}

// ---------------------------------------------------------------------------
// Kernel 2: out[b, h*256+d] = sum_n x[b*360+n, d] * attn[n, h]
// One CTA per graph. 128 threads, each owns a d-pair (float2 of x).
// Inner loop: 1x LDG.64 + 4x broadcast LDS.128 + 8x packed f32x2 FMA.
// ---------------------------------------------------------------------------
__device__ __forceinline__ unsigned long long ffma2(
    unsigned long long a, unsigned long long b, unsigned long long c) {
    unsigned long long d;
    asm("fma.rn.f32x2 %0, %1, %2, %3;" : "=l"(d) : "l"(a), "l"(b), "l"(c));
    return d;
}

__global__ void __launch_bounds__(128) pool_k(const float* __restrict__ x,
                                              float* __restrict__ out) {
    __shared__ __align__(16) float2 s_attn[NNODE * NHEAD];  // 23040 B

    const int t = threadIdx.x;
    const int b = blockIdx.x;

    // cooperative smem fill (float4 = 2 float2 per load)
    {
        const float4* g4 = (const float4*)g_attn2;
        float4* s4 = (float4*)s_attn;
        #pragma unroll
        for (int i = t; i < (NNODE * NHEAD) / 2; i += 128)
            s4[i] = g4[i];
    }
    __syncthreads();

    // x viewed as 64-bit lanes: row stride = DFEAT/2 = 128
    const unsigned long long* xp =
        (const unsigned long long*)x + (size_t)b * NNODE * (DFEAT / 2) + t;

    unsigned long long acc[NHEAD];
    #pragma unroll
    for (int h = 0; h < NHEAD; ++h) acc[h] = 0ull;  // packed (+0,+0)

    #pragma unroll 4
    for (int n = 0; n < NNODE; ++n) {
        unsigned long long v = xp[(size_t)n * (DFEAT / 2)];
        const ulonglong2* arow = (const ulonglong2*)(s_attn + n * NHEAD);
        ulonglong2 p0 = arow[0];
        ulonglong2 p1 = arow[1];
        ulonglong2 p2 = arow[2];
        ulonglong2 p3 = arow[3];
        acc[0] = ffma2(v, p0.x, acc[0]);
        acc[1] = ffma2(v, p0.y, acc[1]);
        acc[2] = ffma2(v, p1.x, acc[2]);
        acc[3] = ffma2(v, p1.y, acc[3]);
        acc[4] = ffma2(v, p2.x, acc[4]);
        acc[5] = ffma2(v, p2.y, acc[5]);
        acc[6] = ffma2(v, p3.x, acc[6]);
        acc[7] = ffma2(v, p3.y, acc[7]);
    }

    // out[b, h*256 + 2t .. 2t+1]  -> as 64-bit lanes: b*1024 + h*128 + t
    unsigned long long* o =
        (unsigned long long*)out + (size_t)b * (NHEAD * DFEAT / 2) + t;
    #pragma unroll
    for (int h = 0; h < NHEAD; ++h)
        o[h * (DFEAT / 2)] = acc[h];
}

extern "C" void kernel_launch(void* const* d_in, const int* in_sizes, int n_in,
                              void* d_out, int out_size) {
    const float* x = (const float*)d_in[0];   // [B*N, D] fp32
    // d_in[1] = batch (int64) — structure is exactly repeat(arange(B), N); unused
    const float* w = (const float*)d_in[2];   // [N, H] fp32
    float* out = (float*)d_out;               // [B, H*D] fp32

    softmax_k<<<1, 256>>>(w);
    pool_k<<<BATCH, 128>>>(x, out);
}